// round 5
// baseline (speedup 1.0000x reference)
#include <cuda_runtime.h>
#include <cuda_fp16.h>
#include <cstdint>

// ---------------- problem constants ----------------
#define KH_ 9
#define KW_ 9
#define IC_ 25
#define OC_ 100
#define H_  256
#define W_  256
#define OH_ 248
#define OW_ 248
#define B_  8

// ---------------- GEMM config ----------------
#define KWP 10            // kw padded 9 -> 10 (keeps (kw,kw+1) pairs intra-row)
#define NOC 112           // oc padded 100 -> 112 (14 n8 chunks)
#define APITCH 272        // fp16 elems per ic row
#define AROWB (APITCH*2)  // 544 B  (136 words = 8 banks stride)
#define BPITCH 264        // fp16 elems per oc row
#define BROWB (BPITCH*2)  // 528 B  (132 words = 4 banks stride -> conflict-free)
#define NTHR 256

// smem layout (bytes)
#define SM_BIAS 0
#define SM_A    512
#define SM_AO   (SM_A + 26*AROWB)          // odd-shift copy
#define SM_B    (SM_A + 2*26*AROWB)        // 512 + 28288 = 28800
#define SMEM_TOTAL (SM_B + 2*NOC*BROWB)    // 28800 + 118272 = 147072

// pre-split, pre-padded weights: [kh][hi/lo][oc][k = ic*10+kw]
__device__ __align__(16) __half g_w[KH_][2][NOC][BPITCH];

// ---------------- helpers ----------------
__device__ __forceinline__ uint32_t smem_u32(const void* p) {
    uint32_t a;
    asm("{ .reg .u64 t; cvta.to.shared.u64 t, %1; cvt.u32.u64 %0, t; }" : "=r"(a) : "l"(p));
    return a;
}

__device__ __forceinline__ uint32_t lds32(uint32_t a) {
    uint32_t v;
    asm volatile("ld.shared.b32 %0, [%1];" : "=r"(v) : "r"(a));
    return v;
}

__device__ __forceinline__ void mma16816(float* d, const uint32_t* a,
                                         uint32_t b0, uint32_t b1) {
    asm volatile(
        "mma.sync.aligned.m16n8k16.row.col.f32.f16.f16.f32 "
        "{%0,%1,%2,%3}, {%4,%5,%6,%7}, {%8,%9}, {%0,%1,%2,%3};"
        : "+f"(d[0]), "+f"(d[1]), "+f"(d[2]), "+f"(d[3])
        : "r"(a[0]), "r"(a[1]), "r"(a[2]), "r"(a[3]), "r"(b0), "r"(b1));
}

// ---------------- weight prep ----------------
__global__ void prep_w(const float* __restrict__ wt) {
    int idx = blockIdx.x * blockDim.x + threadIdx.x;
    if (idx >= KH_ * NOC * BPITCH) return;
    int kh = idx / (NOC * BPITCH);
    int r  = idx % (NOC * BPITCH);
    int oc = r / BPITCH;
    int k  = r % BPITCH;
    float w = 0.f;
    if (oc < OC_ && k < IC_ * KWP) {
        int ic = k / KWP, kw = k % KWP;
        if (kw < KW_)
            w = wt[(((size_t)oc * IC_ + ic) * KH_ + kh) * KW_ + kw];
    }
    __half hi = __float2half_rn(w);
    __half lo = __float2half_rn(w - __half2float(hi));
    g_w[kh][0][oc][k] = hi;
    g_w[kh][1][oc][k] = lo;
}

// ---------------- main kernel ----------------
// block = one output row (b, y): 256(px,pad) x 112(oc,pad), K loop over kh, kc.
// 8 warps: wm = wid&3 (4 M-frags each), wn = wid>>2 (7 n8-chunks each).
__global__ __launch_bounds__(NTHR, 1)
void conv_hmma(const float* __restrict__ in,
               const float* __restrict__ bias,
               float* __restrict__ out) {
    extern __shared__ char smem[];
    const uint32_t sb = smem_u32(smem);
    const int tid = threadIdx.x;
    const int lid = tid & 31;
    const int wid = tid >> 5;
    const int wm = wid & 3;
    const int wn = wid >> 2;
    const int g  = lid >> 2;          // row/col group 0..7
    const int c4 = (lid & 3) << 1;    // k-pair base 0,2,4,6
    const int y = blockIdx.x;
    const int b = blockIdx.y;

    // zero A buffers (pads stay zero across kh) + stage bias
#pragma unroll 1
    for (int i = tid; i < (2 * 26 * AROWB) / 16; i += NTHR)
        *(uint4*)(smem + SM_A + i * 16) = make_uint4(0, 0, 0, 0);
    if (tid < NOC)
        *(float*)(smem + SM_BIAS + tid * 4) = (tid < OC_) ? bias[tid] : 0.f;
    __syncthreads();

    // per-thread A row base addresses (8): parity of px == parity of g
    const uint32_t abase = sb + ((g & 1) ? (SM_AO - 2) : SM_A);
    uint32_t apx[4][2];
#pragma unroll
    for (int m = 0; m < 4; ++m)
#pragma unroll
        for (int h = 0; h < 2; ++h)
            apx[m][h] = abase + (uint32_t)(((wm * 4 + m) * 16 + g + h * 8) * 2);

    float acc[4][7][4];
#pragma unroll
    for (int m = 0; m < 4; ++m)
#pragma unroll
        for (int n = 0; n < 7; ++n)
#pragma unroll
            for (int q = 0; q < 4; ++q)
                acc[m][n][q] = 0.f;

    // B base: oc = (wn*7+nc)*8 + g ; k-col byte offset c4*2 folded in
    const uint32_t bbase = sb + SM_B + (uint32_t)((wn * 56 + g) * BROWB + c4 * 2);

#pragma unroll 1
    for (int kh = 0; kh < KH_; ++kh) {
        // ---- stage raw input row (fp32 -> fp16, two shift copies) ----
        {
            const float* rp = in + (((size_t)(b * IC_)) * H_ + (size_t)(y + kh)) * W_ + tid;
#pragma unroll 1
            for (int ic = 0; ic < IC_; ++ic) {
                float v = rp[(size_t)ic * (H_ * W_)];
                __half hv = __float2half_rn(v);
                *(__half*)(smem + SM_A + ic * AROWB + tid * 2) = hv;
                if (tid > 0)
                    *(__half*)(smem + SM_AO + ic * AROWB + (tid - 1) * 2) = hv;
            }
        }
        // ---- stage B (hi+lo, 118272 B) via cp.async from L2-hot g_w ----
        {
            const char* src = (const char*)(&g_w[kh][0][0][0]);
            const uint32_t dst = sb + SM_B;
#pragma unroll 1
            for (int i = tid; i < (2 * NOC * BROWB) / 16; i += NTHR) {
                asm volatile("cp.async.cg.shared.global [%0], [%1], 16;"
                             :: "r"(dst + (uint32_t)(i * 16)), "l"(src + i * 16));
            }
            asm volatile("cp.async.commit_group;" ::: "memory");
            asm volatile("cp.async.wait_group 0;" ::: "memory");
        }
        __syncthreads();

        // ---- compute: 16 kc chunks, A frags reused across 2 passes x 7 nc ----
#pragma unroll 1
        for (int kc = 0; kc < 16; ++kc) {
            const int k0 = kc * 16 + c4;
            const int k1 = k0 + 8;
            const int ic0 = (k0 * 6554) >> 16;   // k0 / 10
            const int ic1 = (k1 * 6554) >> 16;
            const uint32_t koff0 = (uint32_t)(ic0 * AROWB + (k0 - ic0 * KWP) * 2);
            const uint32_t koff1 = (uint32_t)(ic1 * AROWB + (k1 - ic1 * KWP) * 2);

            uint32_t a[4][4];
#pragma unroll
            for (int m = 0; m < 4; ++m) {
                a[m][0] = lds32(apx[m][0] + koff0);
                a[m][1] = lds32(apx[m][1] + koff0);
                a[m][2] = lds32(apx[m][0] + koff1);
                a[m][3] = lds32(apx[m][1] + koff1);
            }

            const uint32_t bk = bbase + (uint32_t)(kc * 32);
#pragma unroll
            for (int pass = 0; pass < 2; ++pass) {
#pragma unroll
                for (int nc = 0; nc < 7; ++nc) {
                    uint32_t baddr = bk + (uint32_t)(pass * (NOC * BROWB) + nc * (8 * BROWB));
                    uint32_t b0 = lds32(baddr);
                    uint32_t b1 = lds32(baddr + 16);
#pragma unroll
                    for (int m = 0; m < 4; ++m)
                        mma16816(acc[m][nc], a[m], b0, b1);
                }
            }
        }
        __syncthreads();
    }

    // ---- epilogue: bias + masked stores ----
#pragma unroll
    for (int m = 0; m < 4; ++m) {
        const int px = (wm * 4 + m) * 16 + g;
#pragma unroll
        for (int nc = 0; nc < 7; ++nc) {
            const int oc = (wn * 7 + nc) * 8 + c4;
            if (oc < OC_) {
                float bz0 = *(float*)(smem + SM_BIAS + oc * 4);
                float bz1 = *(float*)(smem + SM_BIAS + (oc + 1) * 4);
                size_t base0 = (((size_t)(b * OC_ + oc)) * OH_ + y) * OW_;
                size_t base1 = base0 + (size_t)OH_ * OW_;
                out[base0 + px] = acc[m][nc][0] + bz0;
                out[base1 + px] = acc[m][nc][1] + bz1;
                if (px + 8 < OW_) {
                    out[base0 + px + 8] = acc[m][nc][2] + bz0;
                    out[base1 + px + 8] = acc[m][nc][3] + bz1;
                }
            }
        }
    }
}

// ---------------- launch ----------------
extern "C" void kernel_launch(void* const* d_in, const int* in_sizes, int n_in,
                              void* d_out, int out_size) {
    const float* pic  = (const float*)d_in[0];   // [8,25,256,256]
    const float* wt   = (const float*)d_in[1];   // [100,25,9,9]
    const float* bias = (const float*)d_in[2];   // [100]
    float* out = (float*)d_out;                  // [8,100,248,248]

    int n = KH_ * NOC * BPITCH;
    prep_w<<<(n + 255) / 256, 256>>>(wt);

    cudaFuncSetAttribute(conv_hmma, cudaFuncAttributeMaxDynamicSharedMemorySize, SMEM_TOTAL);
    dim3 grid(OH_, B_);
    conv_hmma<<<grid, NTHR, SMEM_TOTAL>>>(pic, bias, out);
}

// round 6
// speedup vs baseline: 1.0579x; 1.0579x over previous
#include <cuda_runtime.h>
#include <cuda_fp16.h>
#include <cstdint>

// ---------------- problem constants ----------------
#define KH_ 9
#define KW_ 9
#define IC_ 25
#define OC_ 100
#define H_  256
#define W_  256
#define OH_ 248
#define OW_ 248
#define B_  8

// ---------------- GEMM config ----------------
#define KWP 10            // kw padded 9 -> 10 (keeps even-k pairs intra-row & aligned)
#define NOC 112           // oc padded 100 -> 112 (14 n8 chunks)
#define MT  128           // pixels per tile
#define APITCH 144        // fp16 elems per ic row (>=137)
#define AROWB (APITCH*2)  // 288 B
#define BPITCH 264        // fp16 elems per oc row (k: 25*10=250 -> 264 pad)
#define BROWB (BPITCH*2)  // 528 B (132 words = 4-bank stride -> conflict-free)
#define NTHR 256
#define NAROWS 26         // 25 ic + 1 zero row for k-pad region (k 250..255 -> ic 25)

// smem layout (bytes)
#define SM_BIAS 0
#define SM_A    512
#define SM_AO   (SM_A + NAROWS*AROWB)       // odd-shift copy
#define SM_B    (SM_A + 2*NAROWS*AROWB)     // 512 + 14976 = 15488
#define SMEM_TOTAL (SM_B + NOC*BROWB)       // 15488 + 59136 = 74624  -> 2 CTAs/SM

// pre-split, pre-padded weights: [kh][hi/lo][oc][k = ic*10+kw]
__device__ __align__(16) __half g_w[KH_][2][NOC][BPITCH];

// ---------------- helpers ----------------
__device__ __forceinline__ uint32_t smem_u32(const void* p) {
    uint32_t a;
    asm("{ .reg .u64 t; cvta.to.shared.u64 t, %1; cvt.u32.u64 %0, t; }" : "=r"(a) : "l"(p));
    return a;
}

__device__ __forceinline__ uint32_t lds32(uint32_t a) {
    uint32_t v;
    asm volatile("ld.shared.b32 %0, [%1];" : "=r"(v) : "r"(a));
    return v;
}

__device__ __forceinline__ void mma16816(float* d, const uint32_t* a,
                                         uint32_t b0, uint32_t b1) {
    asm volatile(
        "mma.sync.aligned.m16n8k16.row.col.f32.f16.f16.f32 "
        "{%0,%1,%2,%3}, {%4,%5,%6,%7}, {%8,%9}, {%0,%1,%2,%3};"
        : "+f"(d[0]), "+f"(d[1]), "+f"(d[2]), "+f"(d[3])
        : "r"(a[0]), "r"(a[1]), "r"(a[2]), "r"(a[3]), "r"(b0), "r"(b1));
}

// ---------------- weight prep ----------------
__global__ void prep_w(const float* __restrict__ wt) {
    int idx = blockIdx.x * blockDim.x + threadIdx.x;
    if (idx >= KH_ * NOC * BPITCH) return;
    int kh = idx / (NOC * BPITCH);
    int r  = idx % (NOC * BPITCH);
    int oc = r / BPITCH;
    int k  = r % BPITCH;
    float w = 0.f;
    if (oc < OC_ && k < IC_ * KWP) {
        int ic = k / KWP, kw = k % KWP;
        if (kw < KW_)
            w = wt[(((size_t)oc * IC_ + ic) * KH_ + kh) * KW_ + kw];
    }
    __half hi = __float2half_rn(w);
    __half lo = __float2half_rn(w - __half2float(hi));
    g_w[kh][0][oc][k] = hi;
    g_w[kh][1][oc][k] = lo;
}

// ---------------- main kernel ----------------
// block = 128 px (x strip) x 112 oc of one output row (b, y).
// 8 warps: wm = wid&3 (2 m16-frags each), wn = wid>>2 (7 n8-chunks each).
// Per kh: two sub-steps (hi pass, lo pass), each stages its B tile then runs
// 16 k16-chunks. 2 CTAs/SM overlap staging with compute.
__global__ __launch_bounds__(NTHR, 2)
void conv_hmma(const float* __restrict__ in,
               const float* __restrict__ bias,
               float* __restrict__ out) {
    extern __shared__ char smem[];
    const uint32_t sb = smem_u32(smem);
    const int tid = threadIdx.x;
    const int lid = tid & 31;
    const int wid = tid >> 5;
    const int wm = wid & 3;
    const int wn = wid >> 2;
    const int g  = lid >> 2;          // row/col group 0..7
    const int c4 = (lid & 3) << 1;    // k-pair base 0,2,4,6
    const int x0 = blockIdx.x ? (OW_ - MT) : 0;   // 0 or 120
    const int y  = blockIdx.y;
    const int b  = blockIdx.z;

    // zero A buffers (pads + zero-row stay zero across kh) + stage bias
#pragma unroll 1
    for (int i = tid; i < (2 * NAROWS * AROWB) / 16; i += NTHR)
        *(uint4*)(smem + SM_A + i * 16) = make_uint4(0, 0, 0, 0);
    if (tid < NOC)
        *(float*)(smem + SM_BIAS + tid * 4) = (tid < OC_) ? bias[tid] : 0.f;
    __syncthreads();

    // per-thread A row base addresses: parity of px == parity of g
    const uint32_t abase = sb + ((g & 1) ? (SM_AO - 2) : SM_A);
    uint32_t apx[2][2];
#pragma unroll
    for (int m = 0; m < 2; ++m)
#pragma unroll
        for (int h = 0; h < 2; ++h)
            apx[m][h] = abase + (uint32_t)(((wm * 2 + m) * 16 + g + h * 8) * 2);

    float acc[2][7][4];
#pragma unroll
    for (int m = 0; m < 2; ++m)
#pragma unroll
        for (int n = 0; n < 7; ++n)
#pragma unroll
            for (int q = 0; q < 4; ++q)
                acc[m][n][q] = 0.f;

    // B base: oc row = (wn*7+nc)*8 + g ; k byte offset c4*2 folded in
    const uint32_t bbase = sb + SM_B + (uint32_t)((wn * 56 + g) * BROWB + c4 * 2);

#pragma unroll 1
    for (int kh = 0; kh < KH_; ++kh) {
#pragma unroll 1
        for (int pass = 0; pass < 2; ++pass) {
            __syncthreads();   // previous compute done with A/B buffers

            // ---- stage B(kh, pass): 59136 B via cp.async ----
            {
                const char* src = (const char*)(&g_w[kh][pass][0][0]);
                const uint32_t dst = sb + SM_B;
#pragma unroll 1
                for (int i = tid; i < (NOC * BROWB) / 16; i += NTHR) {
                    asm volatile("cp.async.cg.shared.global [%0], [%1], 16;"
                                 :: "r"(dst + (uint32_t)(i * 16)), "l"(src + i * 16));
                }
                asm volatile("cp.async.commit_group;" ::: "memory");
            }
            // ---- stage A row images (only when kh advances) ----
            if (pass == 0 && tid < MT + KW_ - 1) {  // tid 0..135
                const float* rp = in + (((size_t)(b * IC_)) * H_ + (size_t)(y + kh)) * W_
                                  + x0 + tid;
#pragma unroll 1
                for (int ic = 0; ic < IC_; ++ic) {
                    float v = rp[(size_t)ic * (H_ * W_)];
                    __half hv = __float2half_rn(v);
                    *(__half*)(smem + SM_A + ic * AROWB + tid * 2) = hv;
                    if (tid > 0)
                        *(__half*)(smem + SM_AO + ic * AROWB + (tid - 1) * 2) = hv;
                }
            }
            asm volatile("cp.async.wait_group 0;" ::: "memory");
            __syncthreads();

            // ---- compute: 16 k16 chunks ----
#pragma unroll 1
            for (int kc = 0; kc < 16; ++kc) {
                const int k0 = kc * 16 + c4;
                const int k1 = k0 + 8;
                const int ic0 = (k0 * 6554) >> 16;   // /10
                const int ic1 = (k1 * 6554) >> 16;
                const uint32_t koff0 = (uint32_t)(ic0 * AROWB + (k0 - ic0 * KWP) * 2);
                const uint32_t koff1 = (uint32_t)(ic1 * AROWB + (k1 - ic1 * KWP) * 2);

                uint32_t a[2][4];
#pragma unroll
                for (int m = 0; m < 2; ++m) {
                    a[m][0] = lds32(apx[m][0] + koff0);
                    a[m][1] = lds32(apx[m][1] + koff0);
                    a[m][2] = lds32(apx[m][0] + koff1);
                    a[m][3] = lds32(apx[m][1] + koff1);
                }

                const uint32_t bk = bbase + (uint32_t)(kc * 32);
#pragma unroll
                for (int nc = 0; nc < 7; ++nc) {
                    uint32_t baddr = bk + (uint32_t)(nc * (8 * BROWB));
                    uint32_t b0 = lds32(baddr);
                    uint32_t b1 = lds32(baddr + 16);
                    mma16816(acc[0][nc], a[0], b0, b1);
                    mma16816(acc[1][nc], a[1], b0, b1);
                }
            }
        }
    }

    // ---- epilogue: bias + stores (px always in range; guard oc only) ----
#pragma unroll
    for (int m = 0; m < 2; ++m) {
        const int px = (wm * 2 + m) * 16 + g;
#pragma unroll
        for (int nc = 0; nc < 7; ++nc) {
            const int oc = (wn * 7 + nc) * 8 + c4;
            if (oc < OC_) {
                float bz0 = *(float*)(smem + SM_BIAS + oc * 4);
                float bz1 = *(float*)(smem + SM_BIAS + (oc + 1) * 4);
                size_t base0 = (((size_t)(b * OC_ + oc)) * OH_ + y) * OW_ + x0;
                size_t base1 = base0 + (size_t)OH_ * OW_;
                out[base0 + px]     = acc[m][nc][0] + bz0;
                out[base1 + px]     = acc[m][nc][1] + bz1;
                out[base0 + px + 8] = acc[m][nc][2] + bz0;
                out[base1 + px + 8] = acc[m][nc][3] + bz1;
            }
        }
    }
}

// ---------------- launch ----------------
extern "C" void kernel_launch(void* const* d_in, const int* in_sizes, int n_in,
                              void* d_out, int out_size) {
    const float* pic  = (const float*)d_in[0];   // [8,25,256,256]
    const float* wt   = (const float*)d_in[1];   // [100,25,9,9]
    const float* bias = (const float*)d_in[2];   // [100]
    float* out = (float*)d_out;                  // [8,100,248,248]

    int n = KH_ * NOC * BPITCH;
    prep_w<<<(n + 255) / 256, 256>>>(wt);

    cudaFuncSetAttribute(conv_hmma, cudaFuncAttributeMaxDynamicSharedMemorySize, SMEM_TOTAL);
    dim3 grid(2, OH_, B_);
    conv_hmma<<<grid, NTHR, SMEM_TOTAL>>>(pic, bias, out);
}